// round 10
// baseline (speedup 1.0000x reference)
#include <cuda_runtime.h>
#include <cstdint>

// out[r][c] = in[(2r+1)*8192 + (2c+1)], out is 4096x4096 f32.
//
// MLP=16: each thread issues 16 independent, fully warp-coalesced float4
// loads (stride 128 float4 across one odd input row) before any store.
// Each float4 yields 2 odd-column values -> one float2 store.
// Streaming hints: zero reuse, evict-first.

__global__ void __launch_bounds__(256) downsample_odd_mlp16(
        const float4* __restrict__ in,
        float2* __restrict__ out) {
    // 128 threads per output row, 4096 rows -> 524,288 threads
    int idx = blockIdx.x * blockDim.x + threadIdx.x;
    int r = idx >> 7;          // output row
    int g = idx & 127;         // group within row

    // input row 2r+1: 2048 float4 per row
    const float4* src = in + (long long)(2 * r + 1) * 2048;
    // output row r: 2048 float2 per row
    float2* dst = out + (long long)r * 2048;

    float4 v[16];
#pragma unroll
    for (int k = 0; k < 16; k++)
        v[k] = __ldcs(src + g + 128 * k);

#pragma unroll
    for (int k = 0; k < 16; k++)
        __stcs(dst + g + 128 * k, make_float2(v[k].y, v[k].w));
}

extern "C" void kernel_launch(void* const* d_in, const int* in_sizes, int n_in,
                              void* d_out, int out_size) {
    const float4* in = (const float4*)d_in[0];
    float2* out = (float2*)d_out;

    const long long total = 4096LL * 128;   // 524,288 threads
    int threads = 256;
    int blocks = (int)(total / threads);    // 2048
    downsample_odd_mlp16<<<blocks, threads>>>(in, out);
}

// round 14
// speedup vs baseline: 1.0137x; 1.0137x over previous
#include <cuda_runtime.h>
#include <cstdint>

// out[r][c] = in[(2r+1)*8192 + (2c+1)], out is 4096x4096 f32.
//
// Persistent single-wave grid (148 SMs x 8 blocks x 256 thr), grid-stride
// loop over 1,048,576 work items. Each item: 8 independent fully-coalesced
// float4 loads (stride 256 float4 across one odd input row), front-batched
// (MLP=8), then 8 float2 stores. Streaming hints: zero reuse.

__global__ void __launch_bounds__(256) downsample_odd_persist(
        const float4* __restrict__ in,
        float2* __restrict__ out) {
    const int TOTAL = 4096 * 256;            // work items (thread-equivalents)
    int stride = gridDim.x * blockDim.x;

    for (int idx = blockIdx.x * blockDim.x + threadIdx.x;
         idx < TOTAL; idx += stride) {
        int r = idx >> 8;                    // output row
        int g = idx & 255;                   // group within row

        const float4* src = in + (long long)(2 * r + 1) * 2048;
        float2* dst = out + (long long)r * 2048;

        float4 v0 = __ldcs(src + g);
        float4 v1 = __ldcs(src + g + 256);
        float4 v2 = __ldcs(src + g + 512);
        float4 v3 = __ldcs(src + g + 768);
        float4 v4 = __ldcs(src + g + 1024);
        float4 v5 = __ldcs(src + g + 1280);
        float4 v6 = __ldcs(src + g + 1536);
        float4 v7 = __ldcs(src + g + 1792);

        __stcs(dst + g,        make_float2(v0.y, v0.w));
        __stcs(dst + g + 256,  make_float2(v1.y, v1.w));
        __stcs(dst + g + 512,  make_float2(v2.y, v2.w));
        __stcs(dst + g + 768,  make_float2(v3.y, v3.w));
        __stcs(dst + g + 1024, make_float2(v4.y, v4.w));
        __stcs(dst + g + 1280, make_float2(v5.y, v5.w));
        __stcs(dst + g + 1536, make_float2(v6.y, v6.w));
        __stcs(dst + g + 1792, make_float2(v7.y, v7.w));
    }
}

extern "C" void kernel_launch(void* const* d_in, const int* in_sizes, int n_in,
                              void* d_out, int out_size) {
    const float4* in = (const float4*)d_in[0];
    float2* out = (float2*)d_out;

    // single resident wave: 148 SMs * 8 blocks of 256 threads
    int blocks = 148 * 8;                    // 1184
    downsample_odd_persist<<<blocks, 256>>>(in, out);
}

// round 15
// speedup vs baseline: 1.0645x; 1.0502x over previous
#include <cuda_runtime.h>
#include <cstdint>

// out[r][c] = in[(2r+1)*8192 + (2c+1)], out is 4096x4096 f32.
//
// MLP=8 with warp-contiguous DRAM bursts: each warp's 8 LDG.128 cover one
// contiguous 4KB block of an odd input row (loads at 512B steps), and its
// 8 STG.64 cover one contiguous 2KB block of the output row. All loads
// front-batched before stores. Streaming hints (zero reuse).

__global__ void __launch_bounds__(256) downsample_odd_burst(
        const float4* __restrict__ in,
        float2* __restrict__ out) {
    // 256 threads (8 warps) per output row; 4096 rows.
    int idx = blockIdx.x * blockDim.x + threadIdx.x;
    int r    = idx >> 8;                 // output row
    int tid  = idx & 255;                // thread within row
    int warp = tid >> 5;                 // 0..7: which 4KB block of the row
    int lane = tid & 31;

    // input row 2r+1: 2048 float4 per row; warp block = 256 float4 (4KB)
    const float4* src = in + (long long)(2 * r + 1) * 2048 + warp * 256 + lane;
    // output row r: 2048 float2 per row; warp block = 256 float2 (2KB)
    float2* dst = out + (long long)r * 2048 + warp * 256 + lane;

    // 8 loads: consecutive 512B bursts within the warp's 4KB block
    float4 v0 = __ldcs(src);
    float4 v1 = __ldcs(src + 32);
    float4 v2 = __ldcs(src + 64);
    float4 v3 = __ldcs(src + 96);
    float4 v4 = __ldcs(src + 128);
    float4 v5 = __ldcs(src + 160);
    float4 v6 = __ldcs(src + 192);
    float4 v7 = __ldcs(src + 224);

    __stcs(dst,       make_float2(v0.y, v0.w));
    __stcs(dst + 32,  make_float2(v1.y, v1.w));
    __stcs(dst + 64,  make_float2(v2.y, v2.w));
    __stcs(dst + 96,  make_float2(v3.y, v3.w));
    __stcs(dst + 128, make_float2(v4.y, v4.w));
    __stcs(dst + 160, make_float2(v5.y, v5.w));
    __stcs(dst + 192, make_float2(v6.y, v6.w));
    __stcs(dst + 224, make_float2(v7.y, v7.w));
}

extern "C" void kernel_launch(void* const* d_in, const int* in_sizes, int n_in,
                              void* d_out, int out_size) {
    const float4* in = (const float4*)d_in[0];
    float2* out = (float2*)d_out;

    const long long total = 4096LL * 256;   // 1,048,576 threads
    int threads = 256;
    int blocks = (int)(total / threads);    // 4096
    downsample_odd_burst<<<blocks, threads>>>(in, out);
}